// round 1
// baseline (speedup 1.0000x reference)
#include <cuda_runtime.h>
#include <cuda_bf16.h>
#include <cstdint>

// Problem constants
#define Nn   8192
#define Kk   4
#define Bb   16
#define Dd   512
#define Mm   64
#define DP1  513
#define CAP  1024
#define NA   (Nn*Kk)   // 32768 assignments

// Scratch (device globals — no allocation allowed)
__device__ float g_inv[Mm*Bb];     // 1/col-norm per (expert, b)
__device__ int   g_count[Mm];
__device__ int   g_list[Mm*CAP];   // assignment ids grouped by expert

typedef unsigned long long ull;

// ---- packed f32x2 helpers (sm_100+ PTX) ----
__device__ __forceinline__ ull pk2(float lo, float hi){
    ull v; asm("mov.b64 %0, {%1,%2};" : "=l"(v) : "f"(lo), "f"(hi)); return v;
}
__device__ __forceinline__ void unpk2(ull v, float& lo, float& hi){
    asm("mov.b64 {%0,%1}, %2;" : "=f"(lo), "=f"(hi) : "l"(v));
}
__device__ __forceinline__ void fma2(ull& d, ull a, ull b){
    asm("fma.rn.f32x2 %0, %1, %2, %0;" : "+l"(d) : "l"(a), "l"(b));
}
__device__ __forceinline__ void add2(ull& d, ull a){
    asm("add.rn.f32x2 %0, %0, %1;" : "+l"(d) : "l"(a));
}

// ---------------------------------------------------------------------------
// Kernel 1: column inverse norms (over all D+1 rows) + reset counters
// ---------------------------------------------------------------------------
__global__ void k_norm(const float* __restrict__ U){
    __shared__ float sm[256];
    const int m = blockIdx.x, t = threadIdx.x;
    const int b = t & 15, r0 = t >> 4;
    const float* Um = U + (size_t)m * DP1 * Bb;
    float s = 0.f;
    for (int d = r0; d < DP1; d += 16){
        float v = Um[d*Bb + b];
        s += v*v;
    }
    sm[t] = s;
    __syncthreads();
    if (t < 16){
        float tot = 0.f;
        #pragma unroll
        for (int i = 0; i < 16; i++) tot += sm[t + 16*i];
        float y = rsqrtf(tot);
        y = y * (1.5f - 0.5f*tot*y*y);   // one Newton step for accuracy
        g_inv[m*Bb + t] = y;
    }
    if (t == 0) g_count[m] = 0;
}

// ---------------------------------------------------------------------------
// Kernel 2: counting scatter of assignments into per-expert lists
// ---------------------------------------------------------------------------
__global__ void k_build(const int* __restrict__ idx){
    int a = blockIdx.x * blockDim.x + threadIdx.x;
    if (a < NA){
        int e = idx[a] & 63;
        int pos = atomicAdd(&g_count[e], 1);
        if (pos < CAP) g_list[e*CAP + pos] = a;
    }
}

// ---------------------------------------------------------------------------
// Kernel 3: writes pass. Un in registers (thread owns d=t and d=t+256).
// Per match: broadcast-load h (16 floats), 16 f32x2 FMAs, 2 global reds.
// ---------------------------------------------------------------------------
#define S1 8
__global__ void __launch_bounds__(256) k_writes(const float* __restrict__ h,
                                                const float* __restrict__ U,
                                                float* __restrict__ out){
    const int e   = blockIdx.x >> 3;     // /S1
    const int sub = blockIdx.x & (S1-1);
    const int t   = threadIdx.x;
    const float* Ue = U + (size_t)e * DP1 * Bb;

    // Pre-scaled expert rows for d0=t, d1=t+256, packed as f32x2 pairs
    ull u0[8], u1[8];
    #pragma unroll
    for (int p = 0; p < 8; p++){
        float i0 = g_inv[e*Bb + 2*p];
        float i1 = g_inv[e*Bb + 2*p + 1];
        u0[p] = pk2(Ue[(size_t)t*Bb + 2*p]*i0,         Ue[(size_t)t*Bb + 2*p + 1]*i1);
        u1[p] = pk2(Ue[(size_t)(t+256)*Bb + 2*p]*i0,   Ue[(size_t)(t+256)*Bb + 2*p + 1]*i1);
    }

    int cnt = g_count[e]; if (cnt > CAP) cnt = CAP;
    const int s    = (cnt * sub) / S1;
    const int epos = (cnt * (sub+1)) / S1;

    for (int i = s; i < epos; i++){
        int a = g_list[e*CAP + i];
        const float4* hp = (const float4*)(h + (size_t)a * Bb);
        float4 q0 = __ldg(hp+0), q1 = __ldg(hp+1), q2 = __ldg(hp+2), q3 = __ldg(hp+3);
        ull hh[8] = { pk2(q0.x,q0.y), pk2(q0.z,q0.w), pk2(q1.x,q1.y), pk2(q1.z,q1.w),
                      pk2(q2.x,q2.y), pk2(q2.z,q2.w), pk2(q3.x,q3.y), pk2(q3.z,q3.w) };
        ull acc0 = 0ull, acc1 = 0ull;   // (0.f, 0.f)
        #pragma unroll
        for (int p = 0; p < 8; p++){
            fma2(acc0, u0[p], hh[p]);
            fma2(acc1, u1[p], hh[p]);
        }
        float x, y;
        unpk2(acc0, x, y); float r0 = x + y;
        unpk2(acc1, x, y); float r1 = x + y;
        float* w = out + (size_t)(a >> 2) * Dd;
        atomicAdd(w + t,       r0);   // RED (no return)
        atomicAdd(w + t + 256, r1);
    }
}

// ---------------------------------------------------------------------------
// Kernel 4: recon + loss. Un in SMEM (row pad 20 floats -> conflict-free
// LDS.128), one warp handles 4 matches, butterfly reduce, atomic loss.
// ---------------------------------------------------------------------------
#define S2 4
__global__ void __launch_bounds__(256,2) k_recon(const float* __restrict__ h,
                                                 const float* __restrict__ U,
                                                 const float* __restrict__ w,
                                                 float* __restrict__ loss){
    __shared__ __align__(16) float Us[Dd*20];
    __shared__ float wred[8];
    const int e   = blockIdx.x >> 2;     // /S2
    const int sub = blockIdx.x & (S2-1);
    const float* Ue = U + (size_t)e * DP1 * Bb;

    // cooperative load + normalize into padded smem
    for (int i = threadIdx.x; i < Dd*Bb; i += 256){
        int d = i >> 4, b = i & 15;
        Us[d*20 + b] = Ue[i] * g_inv[e*Bb + b];
    }
    __syncthreads();

    int cnt = g_count[e]; if (cnt > CAP) cnt = CAP;
    const int s    = (cnt * sub) / S2;
    const int epos = (cnt * (sub+1)) / S2;
    const int lane = threadIdx.x & 31;
    const int wid  = threadIdx.x >> 5;

    float lsum = 0.f;

    for (int g0 = s + wid*4; g0 < epos; g0 += 8*4){
        int a_[4]; float vm[4];
        #pragma unroll
        for (int mi = 0; mi < 4; mi++){
            int gi = g0 + mi;
            bool v = gi < epos;
            a_[mi] = g_list[e*CAP + (v ? gi : (epos-1))];
            vm[mi] = v ? 1.f : 0.f;
        }
        const float* w0 = w + (size_t)(a_[0] >> 2) * Dd;
        const float* w1 = w + (size_t)(a_[1] >> 2) * Dd;
        const float* w2 = w + (size_t)(a_[2] >> 2) * Dd;
        const float* w3 = w + (size_t)(a_[3] >> 2) * Dd;

        ull r2[4][8];
        #pragma unroll
        for (int m = 0; m < 4; m++)
            #pragma unroll
            for (int p = 0; p < 8; p++) r2[m][p] = 0ull;

        for (int j = 0; j < 16; j++){
            const int d = lane + 32*j;
            float wv0 = __ldg(w0 + d), wv1 = __ldg(w1 + d);
            float wv2 = __ldg(w2 + d), wv3 = __ldg(w3 + d);
            ull ww0 = pk2(wv0, wv0), ww1 = pk2(wv1, wv1);
            ull ww2 = pk2(wv2, wv2), ww3 = pk2(wv3, wv3);
            const float4* row = (const float4*)&Us[d*20];
            #pragma unroll
            for (int bq = 0; bq < 4; bq++){
                float4 u = row[bq];
                ull uL = pk2(u.x, u.y), uH = pk2(u.z, u.w);
                fma2(r2[0][2*bq], ww0, uL); fma2(r2[0][2*bq+1], ww0, uH);
                fma2(r2[1][2*bq], ww1, uL); fma2(r2[1][2*bq+1], ww1, uH);
                fma2(r2[2][2*bq], ww2, uL); fma2(r2[2][2*bq+1], ww2, uH);
                fma2(r2[3][2*bq], ww3, uL); fma2(r2[3][2*bq+1], ww3, uH);
            }
        }

        // butterfly reduce across the 32 lanes (packed adds)
        #pragma unroll
        for (int ofs = 16; ofs > 0; ofs >>= 1){
            #pragma unroll
            for (int m = 0; m < 4; m++)
                #pragma unroll
                for (int p = 0; p < 8; p++){
                    ull o = __shfl_xor_sync(0xffffffffu, r2[m][p], ofs);
                    add2(r2[m][p], o);
                }
        }

        // loss terms (all lanes compute the same value; lane 0 accumulates)
        float tot = 0.f;
        #pragma unroll
        for (int m = 0; m < 4; m++){
            const float4* hp = (const float4*)(h + (size_t)a_[m] * Bb);
            float4 hq0 = hp[0], hq1 = hp[1], hq2 = hp[2], hq3 = hp[3];
            float hv[16] = { hq0.x,hq0.y,hq0.z,hq0.w, hq1.x,hq1.y,hq1.z,hq1.w,
                             hq2.x,hq2.y,hq2.z,hq2.w, hq3.x,hq3.y,hq3.z,hq3.w };
            float tm = 0.f;
            #pragma unroll
            for (int p = 0; p < 8; p++){
                float rl, rh; unpk2(r2[m][p], rl, rh);
                float d0 = rl - hv[2*p];
                float d1 = rh - hv[2*p+1];
                tm += d0*d0 + d1*d1;
            }
            tot += vm[m] * tm;
        }
        if (lane == 0) lsum += tot;
    }

    if (lane == 0) wred[wid] = lsum;
    __syncthreads();
    if (threadIdx.x == 0){
        float sblk = 0.f;
        #pragma unroll
        for (int i = 0; i < 8; i++) sblk += wred[i];
        atomicAdd(loss, sblk * (1.0f / (float)(Nn*Kk*Bb)));
    }
}

// ---------------------------------------------------------------------------
extern "C" void kernel_launch(void* const* d_in, const int* in_sizes, int n_in,
                              void* d_out, int out_size){
    const float* h   = (const float*)d_in[0];   // (N,K,B) f32
    const int*   idx = (const int*)  d_in[1];   // (N,K) i32
    const float* U   = (const float*)d_in[2];   // (M,D+1,B) f32

    float* out  = (float*)d_out;                // writes (N,D) then loss scalar
    float* loss = out + (out_size - 1);

    cudaMemsetAsync(d_out, 0, (size_t)out_size * sizeof(float));
    k_norm  <<<Mm, 256>>>(U);
    k_build <<<NA/256, 256>>>(idx);
    k_writes<<<Mm*S1, 256>>>(h, U, out);
    k_recon <<<Mm*S2, 256>>>(h, U, out, loss);
}